// round 1
// baseline (speedup 1.0000x reference)
#include <cuda_runtime.h>

#define H 8192
#define W 8192
#define KH 7
#define KW 7
#define OH (H - KH + 1)   // 8186
#define OW (W - KW + 1)   // 8186

#define TILE_X 32
#define TILE_Y 32
#define TPB 128                    // 32 (x) * 4 (y warps)
#define ROWS_PER_THREAD 8          // each thread computes 8 stacked output rows
#define SM_H (TILE_Y + KH - 1)     // 38
#define SM_W (TILE_X + KW - 1)     // 38
#define SM_PITCH 40                // pad to avoid bank conflicts
#define VLEN (ROWS_PER_THREAD + KH - 1)  // 14

__global__ __launch_bounds__(TPB)
void conv7x7_kernel(const float* __restrict__ x,
                    const float* __restrict__ wgt,
                    const float* __restrict__ bias,
                    float* __restrict__ out)
{
    __shared__ float tile[SM_H * SM_PITCH];

    const int tx   = threadIdx.x & 31;   // output column within tile
    const int ty   = threadIdx.x >> 5;   // warp id -> row group
    const int col0 = blockIdx.x * TILE_X;
    const int row0 = blockIdx.y * TILE_Y;

    // Weights in registers (broadcast loads, L1/L2 resident after first wave)
    float wreg[KH * KW];
#pragma unroll
    for (int i = 0; i < KH * KW; i++) wreg[i] = __ldg(&wgt[i]);

    // Cooperative halo-tile load (coalesced; guarded only on boundary blocks)
    const bool interior = (row0 + SM_H <= H) && (col0 + SM_W <= W);
    if (interior) {
#pragma unroll 4
        for (int idx = threadIdx.x; idx < SM_H * SM_W; idx += TPB) {
            const int r = idx / SM_W;
            const int c = idx - r * SM_W;
            tile[r * SM_PITCH + c] = x[(row0 + r) * W + (col0 + c)];
        }
    } else {
        for (int idx = threadIdx.x; idx < SM_H * SM_W; idx += TPB) {
            const int r = idx / SM_W;
            const int c = idx - r * SM_W;
            const int gr = row0 + r;
            const int gc = col0 + c;
            tile[r * SM_PITCH + c] = (gr < H && gc < W) ? x[gr * W + gc] : 0.0f;
        }
    }
    __syncthreads();

    float acc[ROWS_PER_THREAD];
#pragma unroll
    for (int o = 0; o < ROWS_PER_THREAD; o++) acc[o] = 0.0f;

    const int rbase = ty * ROWS_PER_THREAD;

    // Per kernel-column: 14 LDS feed 56 FFMAs (1:4 ratio, FMA-pipe bound)
#pragma unroll
    for (int kc = 0; kc < KW; kc++) {
        float v[VLEN];
#pragma unroll
        for (int t = 0; t < VLEN; t++)
            v[t] = tile[(rbase + t) * SM_PITCH + (tx + kc)];
#pragma unroll
        for (int kr = 0; kr < KH; kr++) {
            const float w = wreg[kr * KW + kc];
#pragma unroll
            for (int o = 0; o < ROWS_PER_THREAD; o++)
                acc[o] = fmaf(v[kr + o], w, acc[o]);
        }
    }

    const float b = __ldg(&bias[0]);
    const int ocol = col0 + tx;
    if (ocol < OW) {
#pragma unroll
        for (int o = 0; o < ROWS_PER_THREAD; o++) {
            const int orow = row0 + rbase + o;
            if (orow < OH) out[orow * OW + ocol] = acc[o] + b;
        }
    }
}

extern "C" void kernel_launch(void* const* d_in, const int* in_sizes, int n_in,
                              void* d_out, int out_size)
{
    const float* x    = (const float*)d_in[0];
    const float* wgt  = (const float*)d_in[1];
    const float* bias = (const float*)d_in[2];
    float* out        = (float*)d_out;

    dim3 block(TPB, 1, 1);
    dim3 grid((OW + TILE_X - 1) / TILE_X, (OH + TILE_Y - 1) / TILE_Y, 1);
    conv7x7_kernel<<<grid, block>>>(x, wgt, bias, out);
}

// round 2
// speedup vs baseline: 1.5511x; 1.5511x over previous
#include <cuda_runtime.h>

#define H 8192
#define W 8192
#define KH 7
#define KW 7
#define OH (H - KH + 1)   // 8186
#define OW (W - KW + 1)   // 8186

#define TILE_X 64          // output columns per block (2 per thread, packed f32x2)
#define TILE_Y 32          // output rows per block
#define TPB   128          // 32 lanes (x, 2 cols each) * 4 warps (y, 8 rows each)
#define RPT   8            // rows per thread
#define SM_H  (TILE_Y + KH - 1)   // 38
#define SM_W  (TILE_X + KW - 1)   // 70
#define SP    72                  // smem row pitch (even, 8B-aligned pairs)
#define VLEN  (RPT + KH - 1)      // 14

typedef unsigned long long u64;

__device__ __forceinline__ u64 fma2(u64 a, u64 b, u64 c) {
    u64 d;
    asm("fma.rn.f32x2 %0, %1, %2, %3;" : "=l"(d) : "l"(a), "l"(b), "l"(c));
    return d;
}
__device__ __forceinline__ u64 splat2(float w) {
    u64 d;
    asm("mov.b64 %0, {%1, %1};" : "=l"(d) : "f"(w));
    return d;
}

__global__ __launch_bounds__(TPB, 6)
void conv7x7_f32x2_kernel(const float* __restrict__ x,
                          const float* __restrict__ wgt,
                          const float* __restrict__ bias,
                          float* __restrict__ out)
{
    __shared__ __align__(16) float smA[SM_H * SP];   // tile
    __shared__ __align__(16) float smB[SM_H * SP];   // tile shifted left by 1 col
    __shared__ float wsm[KH * KW];

    const int tid  = threadIdx.x;
    const int col0 = blockIdx.x * TILE_X;
    const int row0 = blockIdx.y * TILE_Y;

    if (tid < KH * KW) wsm[tid] = wgt[tid];

    // ---- Tile load: division-free, clamped reads (no divergent edge path) ----
    // Main region: cols 0..63. 128 threads = 64 cols x 2 row-phases.
    {
        const int c   = tid & 63;
        const int rph = tid >> 6;          // 0 or 1
        const int gc  = min(col0 + c, W - 1);
#pragma unroll
        for (int r = 0; r < SM_H; r += 2) {
            const int rr = r + rph;        // 0..37
            const int gr = min(row0 + rr, H - 1);
            const float v = __ldg(&x[gr * W + gc]);
            smA[rr * SP + c] = v;
            if (c > 0) smB[rr * SP + c - 1] = v;
        }
    }
    // Halo cols 64..69: 38 rows x 8 col-slots (guarded), shifts only.
#pragma unroll
    for (int k = 0; k < 3; k++) {
        const int idx = tid + k * TPB;     // 0..383
        const int rr  = idx >> 3;
        const int c   = 64 + (idx & 7);
        if (rr < SM_H && c < SM_W) {
            const int gr = min(row0 + rr, H - 1);
            const int gc = min(col0 + c, W - 1);
            const float v = __ldg(&x[gr * W + gc]);
            smA[rr * SP + c] = v;
            smB[rr * SP + c - 1] = v;      // c-1 in 63..68
        }
    }
    __syncthreads();

    // ---- Compute: 2 cols x 8 rows per thread, all math in f32x2 ----
    const int tx    = tid & 31;
    const int rbase = (tid >> 5) * RPT;    // 0,8,16,24
    const int cb    = tx * 2;              // 0..62

    u64 acc[RPT];
#pragma unroll
    for (int o = 0; o < RPT; o++) acc[o] = 0ULL;

    const float* baseA = &smA[rbase * SP + cb];
    const float* baseB = &smB[rbase * SP + cb];

#pragma unroll
    for (int kc = 0; kc < KW; kc++) {
        const float* p = (kc & 1) ? (baseB + (kc - 1)) : (baseA + kc);
        u64 v[VLEN];
#pragma unroll
        for (int t = 0; t < VLEN; t++)
            v[t] = *(const u64*)(p + t * SP);   // aligned LDS.64: {x[c+kc], x[c+kc+1]}
#pragma unroll
        for (int kr = 0; kr < KH; kr++) {
            const u64 w2 = splat2(wsm[kr * KW + kc]);
#pragma unroll
            for (int o = 0; o < RPT; o++)
                acc[o] = fma2(v[kr + o], w2, acc[o]);
        }
    }

    // ---- Epilogue: add bias, STG.64 (pairs never straddle OW=8186, even) ----
    const float b = __ldg(&bias[0]);
    const u64 b2 = splat2(b);
    const int ocol = col0 + cb;
    if (ocol < OW) {
#pragma unroll
        for (int o = 0; o < RPT; o++) {
            const int orow = row0 + rbase + o;
            if (orow < OH) {
                u64 r;
                asm("add.rn.f32x2 %0, %1, %2;" : "=l"(r) : "l"(acc[o]), "l"(b2));
                *(u64*)&out[orow * OW + ocol] = r;
            }
        }
    }
}

extern "C" void kernel_launch(void* const* d_in, const int* in_sizes, int n_in,
                              void* d_out, int out_size)
{
    const float* x    = (const float*)d_in[0];
    const float* wgt  = (const float*)d_in[1];
    const float* bias = (const float*)d_in[2];
    float* out        = (float*)d_out;

    dim3 block(TPB, 1, 1);
    dim3 grid((OW + TILE_X - 1) / TILE_X, (OH + TILE_Y - 1) / TILE_Y, 1);
    conv7x7_f32x2_kernel<<<grid, block>>>(x, wgt, bias, out);
}

// round 3
// speedup vs baseline: 1.7391x; 1.1212x over previous
#include <cuda_runtime.h>

#define H 8192
#define W 8192
#define KH 7
#define KW 7
#define OH (H - KH + 1)   // 8186
#define OW (W - KW + 1)   // 8186

#define TILE_X 64          // 32 lanes * 2 cols (f32x2 pair)
#define TILE_Y 64          // 4 warps * 16 rows
#define TPB   128
#define RPT   16           // rows per thread
#define SM_H  (TILE_Y + KH - 1)   // 70
#define SM_W  (TILE_X + KW - 1)   // 70
#define SP    72                  // smem row pitch (floats)
#define VLEN  (RPT + KH - 1)      // 22

typedef unsigned long long u64;

__device__ __forceinline__ u64 fma2(u64 a, u64 b, u64 c) {
    u64 d;
    asm("fma.rn.f32x2 %0, %1, %2, %3;" : "=l"(d) : "l"(a), "l"(b), "l"(c));
    return d;
}
__device__ __forceinline__ u64 splat2(float w) {
    u64 d;
    asm("mov.b64 %0, {%1, %1};" : "=l"(d) : "f"(w));
    return d;
}

__global__ __launch_bounds__(TPB, 4)
void conv7x7_r16_kernel(const float* __restrict__ x,
                        const float* __restrict__ wgt,
                        const float* __restrict__ bias,
                        float* __restrict__ out)
{
    __shared__ __align__(16) float smA[SM_H * SP];   // tile
    __shared__ __align__(16) float smB[SM_H * SP];   // tile shifted left 1 col
    __shared__ float wsm[KH * KW];

    const int tid  = threadIdx.x;
    const int col0 = blockIdx.x * TILE_X;
    const int row0 = blockIdx.y * TILE_Y;

    if (tid < KH * KW) wsm[tid] = wgt[tid];

    // ---- Tile fill: clamped reads, division-free main region ----
    // Main: cols 0..63, 128 threads = 64 cols x 2 row phases, 35 row-steps.
    {
        const int c   = tid & 63;
        const int rph = tid >> 6;
        const int gc  = min(col0 + c, W - 1);
#pragma unroll
        for (int r = 0; r < SM_H; r += 2) {
            const int rr = r + rph;                    // 0..69
            const int gr = min(row0 + rr, H - 1);
            const float v = __ldg(&x[gr * W + gc]);
            smA[rr * SP + c] = v;
            if (c > 0) smB[rr * SP + c - 1] = v;
        }
    }
    // Halo: cols 64..69, 70 rows x 6 cols = 420 elems.
#pragma unroll
    for (int k = 0; k < 4; k++) {
        const int idx = tid + k * TPB;                 // 0..511
        if (idx < SM_H * 6) {
            const int rr = idx / 6;
            const int c  = 64 + (idx - rr * 6);        // 64..69
            const int gr = min(row0 + rr, H - 1);
            const int gc = min(col0 + c, W - 1);
            const float v = __ldg(&x[gr * W + gc]);
            smA[rr * SP + c] = v;
            smB[rr * SP + c - 1] = v;                  // 63..68
        }
    }
    __syncthreads();

    // ---- Compute: 2 cols x 16 rows per thread, f32x2 throughout ----
    const int tx    = tid & 31;
    const int rbase = (tid >> 5) * RPT;                // 0,16,32,48
    const int cb    = tx * 2;                          // 0..62

    u64 acc[RPT];
#pragma unroll
    for (int o = 0; o < RPT; o++) acc[o] = 0ULL;

    const float* baseA = &smA[rbase * SP + cb];
    const float* baseB = &smB[rbase * SP + cb];

#pragma unroll
    for (int kc = 0; kc < KW; kc++) {
        const float* p = (kc & 1) ? (baseB + (kc - 1)) : (baseA + kc);

        u64 w2[KH];
#pragma unroll
        for (int kr = 0; kr < KH; kr++) w2[kr] = splat2(wsm[kr * KW + kc]);

        u64 v[VLEN];
#pragma unroll
        for (int t = 0; t < VLEN; t++)
            v[t] = *(const u64*)(p + t * SP);          // aligned LDS.64

#pragma unroll
        for (int kr = 0; kr < KH; kr++)
#pragma unroll
            for (int o = 0; o < RPT; o++)
                acc[o] = fma2(v[kr + o], w2[kr], acc[o]);
    }

    // ---- Epilogue: bias add + STG.64 (OW even: pairs never straddle) ----
    const u64 b2 = splat2(__ldg(&bias[0]));
    const int ocol = col0 + cb;
    if (ocol < OW) {
#pragma unroll
        for (int o = 0; o < RPT; o++) {
            const int orow = row0 + rbase + o;
            if (orow < OH) {
                u64 r;
                asm("add.rn.f32x2 %0, %1, %2;" : "=l"(r) : "l"(acc[o]), "l"(b2));
                *(u64*)&out[orow * OW + ocol] = r;
            }
        }
    }
}

extern "C" void kernel_launch(void* const* d_in, const int* in_sizes, int n_in,
                              void* d_out, int out_size)
{
    const float* x    = (const float*)d_in[0];
    const float* wgt  = (const float*)d_in[1];
    const float* bias = (const float*)d_in[2];
    float* out        = (float*)d_out;

    dim3 block(TPB, 1, 1);
    dim3 grid((OW + TILE_X - 1) / TILE_X, (OH + TILE_Y - 1) / TILE_Y, 1);
    conv7x7_r16_kernel<<<grid, block>>>(x, wgt, bias, out);
}